// round 2
// baseline (speedup 1.0000x reference)
#include <cuda_runtime.h>

#define NMAX 100000
#define D 64
#define FULL 0xffffffffu

// Scratch (no device allocation allowed) — 25.6 MB each.
__device__ float g_hidden[NMAX * D];
__device__ float g_support[NMAX * D];

__device__ __forceinline__ float wsum(float v) {
#pragma unroll
    for (int o = 16; o; o >>= 1) v += __shfl_xor_sync(FULL, v, o);
    return v;
}

// artanh with reference clipping (inputs here are norms, >= 0)
__device__ __forceinline__ float artanh_c(float x) {
    return atanhf(fminf(x, 1.0f - 1e-7f));
}

// ---------------------------------------------------------------------------
// Kernel A: fused  mx = x @ W^T  -> mobius_matvec -> logmap0  => g_hidden
//           also zeroes g_support for the same rows.
// One warp handles 4 rows; lane owns features d=lane and d=lane+32.
// Ws in smem is W transposed: Ws[k*64 + d] = W[d*64 + k]  (conflict-free reads)
// ---------------------------------------------------------------------------
__global__ void __launch_bounds__(256) kernelA(
    const float* __restrict__ x, const float* __restrict__ W, int N)
{
    __shared__ float Ws[D * D];
    for (int i = threadIdx.x; i < D * D; i += blockDim.x) {
        int d = i >> 6, k = i & 63;
        Ws[k * D + d] = W[i];
    }
    __syncthreads();

    const int warp = threadIdx.x >> 5;
    const int lane = threadIdx.x & 31;
    const int base = (blockIdx.x * 8 + warp) * 4;
    if (base >= N) return;

    float x0[4], x1[4], a0[4], a1[4];
#pragma unroll
    for (int r = 0; r < 4; r++) {
        int row = base + r;
        bool ok = row < N;
        x0[r] = ok ? x[row * D + lane]      : 0.f;
        x1[r] = ok ? x[row * D + lane + 32] : 0.f;
        a0[r] = 0.f; a1[r] = 0.f;
    }

    // GEMM: a0[r] = mx[row_r][lane], a1[r] = mx[row_r][lane+32]
#pragma unroll 4
    for (int k = 0; k < 32; k++) {
        float w0 = Ws[k * D + lane];
        float w1 = Ws[k * D + lane + 32];
#pragma unroll
        for (int r = 0; r < 4; r++) {
            float xk = __shfl_sync(FULL, x0[r], k);
            a0[r] = fmaf(w0, xk, a0[r]);
            a1[r] = fmaf(w1, xk, a1[r]);
        }
    }
#pragma unroll 4
    for (int k = 0; k < 32; k++) {
        float w0 = Ws[(k + 32) * D + lane];
        float w1 = Ws[(k + 32) * D + lane + 32];
#pragma unroll
        for (int r = 0; r < 4; r++) {
            float xk = __shfl_sync(FULL, x1[r], k);
            a0[r] = fmaf(w0, xk, a0[r]);
            a1[r] = fmaf(w1, xk, a1[r]);
        }
    }

#pragma unroll
    for (int r = 0; r < 4; r++) {
        int row = base + r;
        if (row < N) {   // uniform across warp
            float xn  = fmaxf(sqrtf(wsum(x0[r] * x0[r] + x1[r] * x1[r])), 1e-15f);
            float mxn = fmaxf(sqrtf(wsum(a0[r] * a0[r] + a1[r] * a1[r])), 1e-15f);
            unsigned bz = __ballot_sync(FULL, (a0[r] == 0.f) && (a1[r] == 0.f));
            float scale = tanhf(mxn / xn * artanh_c(xn)) / mxn;
            if (bz == FULL) scale = 0.f;     // jnp.where(all(mx==0), 0, res)
            float r0 = a0[r] * scale, r1 = a1[r] * scale;
            // logmap0
            float pn = fmaxf(sqrtf(wsum(r0 * r0 + r1 * r1)), 1e-15f);
            float hs = artanh_c(pn) / pn;
            g_hidden[row * D + lane]      = r0 * hs;
            g_hidden[row * D + lane + 32] = r1 * hs;
            g_support[row * D + lane]      = 0.f;
            g_support[row * D + lane + 32] = 0.f;
        }
    }
}

// ---------------------------------------------------------------------------
// Kernel B: edge scatter  support[rows[e]] += edge_vals[e] * hidden[cols[e]]
// 16 threads per edge, one float4 per thread, vector red.global.add.v4.f32.
// ---------------------------------------------------------------------------
__global__ void __launch_bounds__(256) kernelB(
    const float* __restrict__ ev, const int* __restrict__ rows,
    const int* __restrict__ cols, int total /* = 16*E */)
{
    int t = blockIdx.x * blockDim.x + threadIdx.x;
    if (t >= total) return;
    int e   = t >> 4;
    int sub = t & 15;
    int c = __ldg(&cols[e]);
    int r = __ldg(&rows[e]);
    float v = __ldg(&ev[e]);
    const float4* hp = reinterpret_cast<const float4*>(g_hidden);
    float4 h = __ldg(&hp[c * 16 + sub]);
    float* dst = &g_support[r * D + sub * 4];
    asm volatile("red.global.add.v4.f32 [%0], {%1, %2, %3, %4};"
                 :: "l"(dst), "f"(v * h.x), "f"(v * h.y), "f"(v * h.z), "f"(v * h.w)
                 : "memory");
}

// ---------------------------------------------------------------------------
// Kernel C: expmap0 -> Act(relu in tangent) -> expmap0 -> proj  => out
// One warp per row.
// ---------------------------------------------------------------------------
__global__ void __launch_bounds__(256) kernelC(float* __restrict__ out, int N)
{
    int row = blockIdx.x * 8 + (threadIdx.x >> 5);
    if (row >= N) return;
    int lane = threadIdx.x & 31;
    float s0 = g_support[row * D + lane];
    float s1 = g_support[row * D + lane + 32];
    // expmap0
    float un = fmaxf(sqrtf(wsum(s0 * s0 + s1 * s1)), 1e-15f);
    float ps = tanhf(un) / un;
    float p0 = s0 * ps, p1 = s1 * ps;
    // relu(logmap0(p))
    float pn = fmaxf(sqrtf(wsum(p0 * p0 + p1 * p1)), 1e-15f);
    float as = artanh_c(pn) / pn;
    float xt0 = fmaxf(as * p0, 0.f), xt1 = fmaxf(as * p1, 0.f);
    // expmap0
    float xn = fmaxf(sqrtf(wsum(xt0 * xt0 + xt1 * xt1)), 1e-15f);
    float os = tanhf(xn) / xn;
    float o0 = os * xt0, o1 = os * xt1;
    // proj to ball of radius (1 - PROJ_EPS)
    float on = fmaxf(sqrtf(wsum(o0 * o0 + o1 * o1)), 1e-15f);
    float mxn = 1.0f - 1e-5f;
    if (on > mxn) { float f = mxn / on; o0 *= f; o1 *= f; }
    out[row * D + lane]      = o0;
    out[row * D + lane + 32] = o1;
}

// ---------------------------------------------------------------------------
extern "C" void kernel_launch(void* const* d_in, const int* in_sizes, int n_in,
                              void* d_out, int out_size)
{
    const float* x    = (const float*)d_in[0];
    const float* W    = (const float*)d_in[1];
    const float* ev   = (const float*)d_in[2];
    const int*   rows = (const int*)d_in[3];
    const int*   cols = (const int*)d_in[4];
    float* out = (float*)d_out;

    int N = in_sizes[0] / D;
    int E = in_sizes[2];

    kernelA<<<(N + 31) / 32, 256>>>(x, W, N);
    int total = E * 16;
    kernelB<<<(total + 255) / 256, 256>>>(ev, rows, cols, total);
    kernelC<<<(N + 7) / 8, 256>>>(out, N);
}

// round 3
// speedup vs baseline: 1.1925x; 1.1925x over previous
#include <cuda_runtime.h>

#define NMAX 100000
#define D 64
#define FULL 0xffffffffu

typedef unsigned long long u64;

// Scratch (no device allocation allowed) — 25.6 MB each.
__device__ float g_hidden[NMAX * D];
__device__ float g_support[NMAX * D];

__device__ __forceinline__ float wsum(float v) {
#pragma unroll
    for (int o = 16; o; o >>= 1) v += __shfl_xor_sync(FULL, v, o);
    return v;
}

__device__ __forceinline__ float artanh_c(float x) {
    return atanhf(fminf(x, 1.0f - 1e-7f));
}

// packed fp32x2 FMA (2x fp32 FMA throughput; PTX-only, no C++ autofuse)
__device__ __forceinline__ u64 ffma2(u64 a, u64 b, u64 c) {
    u64 d;
    asm("fma.rn.f32x2 %0, %1, %2, %3;" : "=l"(d) : "l"(a), "l"(b), "l"(c));
    return d;
}
__device__ __forceinline__ float2 unpack2(u64 v) {
    float2 r;
    asm("mov.b64 {%0, %1}, %2;" : "=f"(r.x), "=f"(r.y) : "l"(v));
    return r;
}

// ---------------------------------------------------------------------------
// Kernel A: fused  mx = x @ W^T -> mobius_matvec -> logmap0  => g_hidden
//           (also zeroes g_support rows).
// Block = 256 thr = 8 warps; warp handles 8 rows as 4 packed row-pairs.
// Lane owns cols (lane, lane+32). Hot loop: 3x LDS.64 + 8x FFMA2 per k.
// Wd[k][c] = {W^T[k][c], W^T[k][c]} duplicated; row padded to 65 (bank-safe).
// Xp[warp][k][p] = {x[r2p][k], x[r2p+1][k]}.
// ---------------------------------------------------------------------------
__global__ void __launch_bounds__(256) kernelA(
    const float* __restrict__ x, const float* __restrict__ W, int N)
{
    __shared__ float2 Wd[D * 65];     // ~33 KB
    __shared__ float2 Xp[8][D][4];    // 16 KB

    const int tid  = threadIdx.x;
    const int warp = tid >> 5;
    const int lane = tid & 31;

    // Load + duplicate W^T: read W[d*64+k] coalesced, write Wd[k*65+d].
    for (int i = tid; i < D * D; i += 256) {
        int d = i >> 6, k = i & 63;
        float w = W[i];
        Wd[k * 65 + d] = make_float2(w, w);
    }

    const int base = (blockIdx.x * 8 + warp) * 8;
    // Pack x row-pairs: lane handles k = lane and lane+32.
#pragma unroll
    for (int p = 0; p < 4; p++) {
        int r0 = base + 2 * p, r1 = r0 + 1;
        float a0 = (r0 < N) ? x[r0 * D + lane]      : 0.f;
        float a1 = (r0 < N) ? x[r0 * D + lane + 32] : 0.f;
        float b0 = (r1 < N) ? x[r1 * D + lane]      : 0.f;
        float b1 = (r1 < N) ? x[r1 * D + lane + 32] : 0.f;
        Xp[warp][lane][p]      = make_float2(a0, b0);
        Xp[warp][lane + 32][p] = make_float2(a1, b1);
    }
    __syncthreads();
    if (base >= N) return;   // no further barriers below

    u64 acc[4][2];
#pragma unroll
    for (int p = 0; p < 4; p++) { acc[p][0] = 0ull; acc[p][1] = 0ull; }

#pragma unroll 16
    for (int k = 0; k < D; k++) {
        const u64* wrow = reinterpret_cast<const u64*>(&Wd[k * 65]);
        u64 w0 = wrow[lane];
        u64 w1 = wrow[lane + 32];
        const u64* xr = reinterpret_cast<const u64*>(&Xp[warp][k][0]);
#pragma unroll
        for (int p = 0; p < 4; p++) {
            u64 xp = xr[p];
            acc[p][0] = ffma2(w0, xp, acc[p][0]);
            acc[p][1] = ffma2(w1, xp, acc[p][1]);
        }
    }

    // Epilogue: per row — mobius scale + logmap0, write hidden, zero support.
#pragma unroll
    for (int p = 0; p < 4; p++) {
        float2 c0 = unpack2(acc[p][0]);   // {mx[r0][lane],    mx[r1][lane]}
        float2 c1 = unpack2(acc[p][1]);   // {mx[r0][lane+32], mx[r1][lane+32]}
#pragma unroll
        for (int q = 0; q < 2; q++) {
            int row = base + 2 * p + q;
            if (row < N) {                 // uniform across warp
                float a0 = q ? c0.y : c0.x;
                float a1 = q ? c1.y : c1.x;
                float x0 = x[row * D + lane];        // L1 hits (loaded above)
                float x1 = x[row * D + lane + 32];
                float xn  = fmaxf(sqrtf(wsum(x0 * x0 + x1 * x1)), 1e-15f);
                float mxn = fmaxf(sqrtf(wsum(a0 * a0 + a1 * a1)), 1e-15f);
                unsigned bz = __ballot_sync(FULL, (a0 == 0.f) && (a1 == 0.f));
                float scale = tanhf(mxn / xn * artanh_c(xn)) / mxn;
                if (bz == FULL) scale = 0.f;
                float r0 = a0 * scale, r1 = a1 * scale;
                float pn = fmaxf(sqrtf(wsum(r0 * r0 + r1 * r1)), 1e-15f);
                float hs = artanh_c(pn) / pn;
                g_hidden[row * D + lane]       = r0 * hs;
                g_hidden[row * D + lane + 32]  = r1 * hs;
                g_support[row * D + lane]      = 0.f;
                g_support[row * D + lane + 32] = 0.f;
            }
        }
    }
}

// ---------------------------------------------------------------------------
// Kernel B: edge scatter  support[rows[e]] += edge_vals[e] * hidden[cols[e]]
// 16 threads per edge, one float4 per thread, vector red.global.add.v4.f32.
// Gathers coalesce to one contiguous 256B segment per edge.
// ---------------------------------------------------------------------------
__global__ void __launch_bounds__(256) kernelB(
    const float* __restrict__ ev, const int* __restrict__ rows,
    const int* __restrict__ cols, int total /* = 16*E */)
{
    int t = blockIdx.x * blockDim.x + threadIdx.x;
    if (t >= total) return;
    int e   = t >> 4;
    int sub = t & 15;
    int c = __ldg(&cols[e]);
    int r = __ldg(&rows[e]);
    float v = __ldg(&ev[e]);
    const float4* hp = reinterpret_cast<const float4*>(g_hidden);
    float4 h = __ldg(&hp[c * 16 + sub]);
    float* dst = &g_support[r * D + sub * 4];
    asm volatile("red.global.add.v4.f32 [%0], {%1, %2, %3, %4};"
                 :: "l"(dst), "f"(v * h.x), "f"(v * h.y), "f"(v * h.z), "f"(v * h.w)
                 : "memory");
}

// ---------------------------------------------------------------------------
// Kernel C: expmap0 -> Act(relu in tangent) -> expmap0 -> proj  => out
// ---------------------------------------------------------------------------
__global__ void __launch_bounds__(256) kernelC(float* __restrict__ out, int N)
{
    int row = blockIdx.x * 8 + (threadIdx.x >> 5);
    if (row >= N) return;
    int lane = threadIdx.x & 31;
    float s0 = g_support[row * D + lane];
    float s1 = g_support[row * D + lane + 32];
    float un = fmaxf(sqrtf(wsum(s0 * s0 + s1 * s1)), 1e-15f);
    float ps = tanhf(un) / un;
    float p0 = s0 * ps, p1 = s1 * ps;
    float pn = fmaxf(sqrtf(wsum(p0 * p0 + p1 * p1)), 1e-15f);
    float as = artanh_c(pn) / pn;
    float xt0 = fmaxf(as * p0, 0.f), xt1 = fmaxf(as * p1, 0.f);
    float xn = fmaxf(sqrtf(wsum(xt0 * xt0 + xt1 * xt1)), 1e-15f);
    float os = tanhf(xn) / xn;
    float o0 = os * xt0, o1 = os * xt1;
    float on = fmaxf(sqrtf(wsum(o0 * o0 + o1 * o1)), 1e-15f);
    float mxn = 1.0f - 1e-5f;
    if (on > mxn) { float f = mxn / on; o0 *= f; o1 *= f; }
    out[row * D + lane]      = o0;
    out[row * D + lane + 32] = o1;
}

// ---------------------------------------------------------------------------
extern "C" void kernel_launch(void* const* d_in, const int* in_sizes, int n_in,
                              void* d_out, int out_size)
{
    const float* x    = (const float*)d_in[0];
    const float* W    = (const float*)d_in[1];
    const float* ev   = (const float*)d_in[2];
    const int*   rows = (const int*)d_in[3];
    const int*   cols = (const int*)d_in[4];
    float* out = (float*)d_out;

    int N = in_sizes[0] / D;
    int E = in_sizes[2];

    kernelA<<<(N + 63) / 64, 256>>>(x, W, N);
    int total = E * 16;
    kernelB<<<(total + 255) / 256, 256>>>(ev, rows, cols, total);
    kernelC<<<(N + 7) / 8, 256>>>(out, N);
}